// round 6
// baseline (speedup 1.0000x reference)
#include <cuda_runtime.h>
#include <cuda_fp16.h>
#include <math.h>
#include <stdint.h>

#define T_TOK 1024
#define HID   2048
#define NEXP  16
#define TOPK  4
#define IEXP  1408
#define ISH   2816

// ---------------- scratch (__device__ globals) ----------------
__device__ __align__(1024) __half g_w1h[(size_t)NEXP * 2 * IEXP * HID];
__device__ __align__(1024) __half g_w2h[(size_t)NEXP * HID * IEXP];
__device__ __align__(1024) __half g_wsgh[(size_t)2 * ISH * HID];
__device__ __align__(1024) __half g_wsdh[(size_t)HID * ISH];
__device__ __align__(1024) __half g_xh[(size_t)T_TOK * HID];
__device__ __align__(1024) __half g_xg[(size_t)NEXP * T_TOK * HID];
__device__ __align__(1024) __half g_acth[(size_t)NEXP * T_TOK * IEXP];
__device__ __align__(1024) __half g_ashh[(size_t)T_TOK * ISH];
__device__ float g_ysc[(size_t)NEXP * T_TOK * HID];
__device__ float g_sout[(size_t)T_TOK * HID];
__device__ int   g_cnt[NEXP];
__device__ int   g_te[T_TOK * TOPK];
__device__ int   g_slot[T_TOK * TOPK];
__device__ float g_tw[T_TOK * TOPK];

// ---------------- PTX helpers (plain sm_80-era PTX only) ----------------
__device__ __forceinline__ uint32_t smem_u32(const void* p) {
    uint32_t a;
    asm("{ .reg .u64 t; cvta.to.shared.u64 t, %1; cvt.u32.u64 %0, t; }" : "=r"(a) : "l"(p));
    return a;
}
#define CP16(dst, src) asm volatile("cp.async.cg.shared.global [%0], [%1], 16;" :: "r"(dst), "l"(src) : "memory")
#define CPCOMMIT()     asm volatile("cp.async.commit_group;" ::: "memory")
#define CPWAIT(n)      asm volatile("cp.async.wait_group %0;" :: "n"(n) : "memory")

__device__ __forceinline__ void ldsm4(uint32_t addr, uint32_t& r0, uint32_t& r1,
                                      uint32_t& r2, uint32_t& r3) {
    asm volatile("ldmatrix.sync.aligned.m8n8.x4.shared.b16 {%0,%1,%2,%3}, [%4];"
                 : "=r"(r0), "=r"(r1), "=r"(r2), "=r"(r3) : "r"(addr));
}
__device__ __forceinline__ void mma16816(float* c, uint32_t a0, uint32_t a1, uint32_t a2,
                                         uint32_t a3, uint32_t b0, uint32_t b1) {
    asm volatile(
        "mma.sync.aligned.m16n8k16.row.col.f32.f16.f16.f32 "
        "{%0,%1,%2,%3}, {%4,%5,%6,%7}, {%8,%9}, {%0,%1,%2,%3};"
        : "+f"(c[0]), "+f"(c[1]), "+f"(c[2]), "+f"(c[3])
        : "r"(a0), "r"(a1), "r"(a2), "r"(a3), "r"(b0), "r"(b1));
}

#define SWZ(o) ((o) ^ (((o) >> 3) & 0x70))
#define NSTAGE 3
#define STAGE_B 49152          // 32KB A (256 rows x 128B) + 16KB B (128 rows x 128B)
#define SMEM_DYN (NSTAGE * STAGE_B + 1024)

// ---------------- fp32 -> fp16 conversion ----------------
__global__ void conv_kernel(const float* __restrict__ src, __half* __restrict__ dst) {
    size_t i = ((size_t)blockIdx.x * 256 + threadIdx.x) * 8;
    float4 a = *(const float4*)(src + i);
    float4 b = *(const float4*)(src + i + 4);
    __half2 h0 = __floats2half2_rn(a.x, a.y), h1 = __floats2half2_rn(a.z, a.w);
    __half2 h2 = __floats2half2_rn(b.x, b.y), h3 = __floats2half2_rn(b.z, b.w);
    uint4 o;
    o.x = *(uint32_t*)&h0; o.y = *(uint32_t*)&h1; o.z = *(uint32_t*)&h2; o.w = *(uint32_t*)&h3;
    *(uint4*)(dst + i) = o;
}

__global__ void zero_kernel() { if (threadIdx.x < NEXP) g_cnt[threadIdx.x] = 0; }

// ---------------- router (fp32, unchanged) ----------------
__global__ void router_kernel(const float* __restrict__ x, const float* __restrict__ Wg) {
    int t = blockIdx.x;
    const float* xr = x + (size_t)t * HID;
    float acc[NEXP];
#pragma unroll
    for (int e = 0; e < NEXP; e++) acc[e] = 0.f;
    for (int h = threadIdx.x; h < HID; h += 128) {
        float xv = xr[h];
        const float* wr = Wg + (size_t)h * NEXP;
#pragma unroll
        for (int e = 0; e < NEXP; e++) acc[e] = fmaf(xv, wr[e], acc[e]);
    }
    __shared__ float red[128 * NEXP];
#pragma unroll
    for (int e = 0; e < NEXP; e++) red[threadIdx.x * NEXP + e] = acc[e];
    __syncthreads();
    __shared__ float logits[NEXP];
    if (threadIdx.x < NEXP) {
        float s = 0.f;
        for (int i = 0; i < 128; i++) s += red[i * NEXP + threadIdx.x];
        logits[threadIdx.x] = s;
    }
    __syncthreads();
    if (threadIdx.x == 0) {
        float lv[NEXP];
#pragma unroll
        for (int e = 0; e < NEXP; e++) lv[e] = logits[e];
        int ids[TOPK]; float vals[TOPK];
        bool used[NEXP];
#pragma unroll
        for (int e = 0; e < NEXP; e++) used[e] = false;
        for (int k = 0; k < TOPK; k++) {
            int bi = 0; float bv = -3.4e38f;
            for (int e = 0; e < NEXP; e++)
                if (!used[e] && lv[e] > bv) { bv = lv[e]; bi = e; }
            used[bi] = true; ids[k] = bi; vals[k] = bv;
        }
        float m = vals[0], ssum = 0.f, wv[TOPK];
        for (int k = 0; k < TOPK; k++) { wv[k] = expf(vals[k] - m); ssum += wv[k]; }
        float inv = 1.f / ssum;
        for (int k = 0; k < TOPK; k++) {
            int e = ids[k];
            int slot = atomicAdd(&g_cnt[e], 1);
            g_te[t * TOPK + k]   = e;
            g_slot[t * TOPK + k] = slot;
            g_tw[t * TOPK + k]   = wv[k] * inv;
        }
    }
}

// ---------------- gather x rows (fp16) into per-expert contiguous buffers ----------------
__global__ void gather_kernel() {
    int b = blockIdx.x;
    int t = b >> 2, k = b & 3;
    int e = g_te[t * TOPK + k], slot = g_slot[t * TOPK + k];
    const uint4* src = (const uint4*)(g_xh + (size_t)t * HID);
    uint4* dst = (uint4*)(g_xg + ((size_t)e * T_TOK + slot) * HID);
    dst[threadIdx.x] = src[threadIdx.x];
}

// ---------------- gemm1 (mma.sync): block 256 rows x 64 out-cols (B tile = 64 gate + 64 up rows) ----
// 8 warps as 4m x 2n; warp tile = 64 rows x (32 gate + 32 up cols), silu*mul fused in regs.
__global__ void __launch_bounds__(256) gemm1_mma(int shared_mode) {
    int e = blockIdx.z;
    const __half* A; const __half* B; __half* act;
    int nrows, Ihalf;
    const int K = HID;
    if (shared_mode) { A = g_xh; B = g_wsgh; act = g_ashh; nrows = T_TOK; Ihalf = ISH; }
    else {
        A = g_xg + (size_t)e * T_TOK * HID;
        B = g_w1h + (size_t)e * 2 * IEXP * HID;
        act = g_acth + (size_t)e * T_TOK * IEXP;
        nrows = g_cnt[e]; Ihalf = IEXP;
    }
    int m0 = blockIdx.y * 256;
    if (m0 >= nrows) return;
    int j0 = blockIdx.x * 64;

    extern __shared__ char smraw[];
    uint32_t sb = (smem_u32(smraw) + 1023) & ~1023u;
    int tid = threadIdx.x, lane = tid & 31, wid = tid >> 5;
    int wm = wid & 3, wn = wid >> 2;

    // loaders: A = 2048 16B-chunks (8/thread), B = 1024 chunks (4/thread)
    const __half* asrc[8]; uint32_t aswz[8];
#pragma unroll
    for (int i = 0; i < 8; i++) {
        int c = tid + i * 256;
        int row = c >> 3, c16 = c & 7;
        asrc[i] = A + (size_t)(m0 + row) * K + c16 * 8;
        aswz[i] = SWZ((uint32_t)(row * 128 + c16 * 16));
    }
    const __half* bsrc[4]; uint32_t bswz[4];
#pragma unroll
    for (int i = 0; i < 4; i++) {
        int c = tid + i * 256;
        int row = c >> 3, c16 = c & 7;
        int brow = (row < 64) ? (j0 + row) : (Ihalf + j0 + row - 64);
        bsrc[i] = B + (size_t)brow * K + c16 * 8;
        bswz[i] = SWZ((uint32_t)(row * 128 + c16 * 16));
    }

    const int KT = K / 64;
    for (int s = 0; s < NSTAGE - 1; s++) {
        uint32_t sA = sb + s * STAGE_B, sB = sA + 32768;
        int ko = s * 64;
#pragma unroll
        for (int i = 0; i < 8; i++) CP16(sA + aswz[i], asrc[i] + ko);
#pragma unroll
        for (int i = 0; i < 4; i++) CP16(sB + bswz[i], bsrc[i] + ko);
        CPCOMMIT();
    }

    // ct[mi][ni][4]: mi 0..3 (16-row tiles), ni 0..3 gate, 4..7 up
    float ct[4][8][4];
#pragma unroll
    for (int mi = 0; mi < 4; mi++)
#pragma unroll
        for (int j = 0; j < 8; j++)
#pragma unroll
            for (int q = 0; q < 4; q++) ct[mi][j][q] = 0.f;

    uint32_t l15 = (uint32_t)(lane & 15);
    uint32_t kcb = ((lane >> 4) << 4);

    for (int kt = 0; kt < KT; kt++) {
        CPWAIT(1);
        __syncthreads();
        uint32_t sA = sb + (kt % NSTAGE) * STAGE_B, sB = sA + 32768;
#pragma unroll
        for (int ks = 0; ks < 4; ks++) {
            uint32_t a[4][4];
#pragma unroll
            for (int mi = 0; mi < 4; mi++)
                ldsm4(sA + SWZ((uint32_t)((wm * 64 + mi * 16 + l15) * 128) + ks * 32 + kcb),
                      a[mi][0], a[mi][1], a[mi][2], a[mi][3]);
#pragma unroll
            for (int bb = 0; bb < 2; bb++) {   // gate rows
                uint32_t b0, b1, b2, b3;
                ldsm4(sB + SWZ((uint32_t)((wn * 32 + bb * 16 + l15) * 128) + ks * 32 + kcb), b0, b1, b2, b3);
#pragma unroll
                for (int mi = 0; mi < 4; mi++) {
                    mma16816(ct[mi][2 * bb],     a[mi][0], a[mi][1], a[mi][2], a[mi][3], b0, b2);
                    mma16816(ct[mi][2 * bb + 1], a[mi][0], a[mi][1], a[mi][2], a[mi][3], b1, b3);
                }
            }
#pragma unroll
            for (int bb = 0; bb < 2; bb++) {   // up rows (B smem rows 64..127)
                uint32_t b0, b1, b2, b3;
                ldsm4(sB + SWZ((uint32_t)((64 + wn * 32 + bb * 16 + l15) * 128) + ks * 32 + kcb), b0, b1, b2, b3);
#pragma unroll
                for (int mi = 0; mi < 4; mi++) {
                    mma16816(ct[mi][4 + 2 * bb],     a[mi][0], a[mi][1], a[mi][2], a[mi][3], b0, b2);
                    mma16816(ct[mi][4 + 2 * bb + 1], a[mi][0], a[mi][1], a[mi][2], a[mi][3], b1, b3);
                }
            }
        }
        __syncthreads();
        int nc = kt + NSTAGE - 1;
        if (nc < KT) {
            uint32_t dA = sb + (nc % NSTAGE) * STAGE_B, dB = dA + 32768;
            int ko = nc * 64;
#pragma unroll
            for (int i = 0; i < 8; i++) CP16(dA + aswz[i], asrc[i] + ko);
#pragma unroll
            for (int i = 0; i < 4; i++) CP16(dB + bswz[i], bsrc[i] + ko);
        }
        CPCOMMIT();
    }

#pragma unroll
    for (int mi = 0; mi < 4; mi++) {
        int row = m0 + wm * 64 + mi * 16 + (lane >> 2);
#pragma unroll
        for (int ni = 0; ni < 4; ni++) {
            int col = j0 + wn * 32 + ni * 8 + (lane & 3) * 2;
            if (row < nrows) {
                float g0 = ct[mi][ni][0], g1 = ct[mi][ni][1];
                float u0 = ct[mi][ni + 4][0], u1 = ct[mi][ni + 4][1];
                __half2 h = __floats2half2_rn(g0 / (1.f + expf(-g0)) * u0,
                                              g1 / (1.f + expf(-g1)) * u1);
                *(__half2*)(act + (size_t)row * Ihalf + col) = h;
            }
            if (row + 8 < nrows) {
                float g0 = ct[mi][ni][2], g1 = ct[mi][ni][3];
                float u0 = ct[mi][ni + 4][2], u1 = ct[mi][ni + 4][3];
                __half2 h = __floats2half2_rn(g0 / (1.f + expf(-g0)) * u0,
                                              g1 / (1.f + expf(-g1)) * u1);
                *(__half2*)(act + (size_t)(row + 8) * Ihalf + col) = h;
            }
        }
    }
}

// ---------------- gemm2 (mma.sync): block 256 x 128, warp 64x64 -> fp32 ----------------
__global__ void __launch_bounds__(256) gemm2_mma(int shared_mode) {
    int e = blockIdx.z;
    const __half* A; const __half* B; float* C;
    int nrows, K;
    if (shared_mode) { A = g_ashh; B = g_wsdh; C = g_sout; nrows = T_TOK; K = ISH; }
    else {
        A = g_acth + (size_t)e * T_TOK * IEXP;
        B = g_w2h + (size_t)e * HID * IEXP;
        C = g_ysc + (size_t)e * T_TOK * HID;
        nrows = g_cnt[e]; K = IEXP;
    }
    int m0 = blockIdx.y * 256;
    if (m0 >= nrows) return;
    int n0 = blockIdx.x * 128;

    extern __shared__ char smraw[];
    uint32_t sb = (smem_u32(smraw) + 1023) & ~1023u;
    int tid = threadIdx.x, lane = tid & 31, wid = tid >> 5;
    int wm = wid & 3, wn = wid >> 2;

    const __half* asrc[8]; uint32_t aswz[8];
#pragma unroll
    for (int i = 0; i < 8; i++) {
        int c = tid + i * 256;
        int row = c >> 3, c16 = c & 7;
        asrc[i] = A + (size_t)(m0 + row) * K + c16 * 8;
        aswz[i] = SWZ((uint32_t)(row * 128 + c16 * 16));
    }
    const __half* bsrc[4]; uint32_t bswz[4];
#pragma unroll
    for (int i = 0; i < 4; i++) {
        int c = tid + i * 256;
        int row = c >> 3, c16 = c & 7;
        bsrc[i] = B + (size_t)(n0 + row) * K + c16 * 8;
        bswz[i] = SWZ((uint32_t)(row * 128 + c16 * 16));
    }

    const int KT = K / 64;
    for (int s = 0; s < NSTAGE - 1; s++) {
        uint32_t sA = sb + s * STAGE_B, sB = sA + 32768;
        int ko = s * 64;
#pragma unroll
        for (int i = 0; i < 8; i++) CP16(sA + aswz[i], asrc[i] + ko);
#pragma unroll
        for (int i = 0; i < 4; i++) CP16(sB + bswz[i], bsrc[i] + ko);
        CPCOMMIT();
    }

    float ct[4][8][4];
#pragma unroll
    for (int mi = 0; mi < 4; mi++)
#pragma unroll
        for (int j = 0; j < 8; j++)
#pragma unroll
            for (int q = 0; q < 4; q++) ct[mi][j][q] = 0.f;

    uint32_t l15 = (uint32_t)(lane & 15);
    uint32_t kcb = ((lane >> 4) << 4);

    for (int kt = 0; kt < KT; kt++) {
        CPWAIT(1);
        __syncthreads();
        uint32_t sA = sb + (kt % NSTAGE) * STAGE_B, sB = sA + 32768;
#pragma unroll
        for (int ks = 0; ks < 4; ks++) {
            uint32_t a[4][4];
#pragma unroll
            for (int mi = 0; mi < 4; mi++)
                ldsm4(sA + SWZ((uint32_t)((wm * 64 + mi * 16 + l15) * 128) + ks * 32 + kcb),
                      a[mi][0], a[mi][1], a[mi][2], a[mi][3]);
#pragma unroll
            for (int bb = 0; bb < 4; bb++) {
                uint32_t b0, b1, b2, b3;
                ldsm4(sB + SWZ((uint32_t)((wn * 64 + bb * 16 + l15) * 128) + ks * 32 + kcb), b0, b1, b2, b3);
#pragma unroll
                for (int mi = 0; mi < 4; mi++) {
                    mma16816(ct[mi][2 * bb],     a[mi][0], a[mi][1], a[mi][2], a[mi][3], b0, b2);
                    mma16816(ct[mi][2 * bb + 1], a[mi][0], a[mi][1], a[mi][2], a[mi][3], b1, b3);
                }
            }
        }
        __syncthreads();
        int nc = kt + NSTAGE - 1;
        if (nc < KT) {
            uint32_t dA = sb + (nc % NSTAGE) * STAGE_B, dB = dA + 32768;
            int ko = nc * 64;
#pragma unroll
            for (int i = 0; i < 8; i++) CP16(dA + aswz[i], asrc[i] + ko);
#pragma unroll
            for (int i = 0; i < 4; i++) CP16(dB + bswz[i], bsrc[i] + ko);
        }
        CPCOMMIT();
    }

#pragma unroll
    for (int mi = 0; mi < 4; mi++) {
        int row = m0 + wm * 64 + mi * 16 + (lane >> 2);
#pragma unroll
        for (int ni = 0; ni < 8; ni++) {
            int col = n0 + wn * 64 + ni * 8 + (lane & 3) * 2;
            if (row < nrows)
                *(float2*)(C + (size_t)row * HID + col) = make_float2(ct[mi][ni][0], ct[mi][ni][1]);
            if (row + 8 < nrows)
                *(float2*)(C + (size_t)(row + 8) * HID + col) = make_float2(ct[mi][ni][2], ct[mi][ni][3]);
        }
    }
}

// ---------------- combine ----------------
__global__ void combine_kernel(float* __restrict__ out) {
    size_t idx = (size_t)blockIdx.x * 256 + threadIdx.x;
    int t = (int)(idx >> 11);
    int h = (int)(idx & 2047);
    float v = g_sout[idx];
#pragma unroll
    for (int k = 0; k < TOPK; k++) {
        int e = g_te[t * TOPK + k];
        int s = g_slot[t * TOPK + k];
        float w = g_tw[t * TOPK + k];
        v = fmaf(w, g_ysc[((size_t)e * T_TOK + s) * HID + h], v);
    }
    out[idx] = v;
}

extern "C" void kernel_launch(void* const* d_in, const int* in_sizes, int n_in,
                              void* d_out, int out_size) {
    const float* x   = (const float*)d_in[0];
    const float* Wg  = (const float*)d_in[1];
    const float* W1  = (const float*)d_in[2];
    const float* W2  = (const float*)d_in[3];
    const float* Wsg = (const float*)d_in[4];
    const float* Wsd = (const float*)d_in[5];
    float* out = (float*)d_out;

    cudaFuncSetAttribute(gemm1_mma, cudaFuncAttributeMaxDynamicSharedMemorySize, SMEM_DYN);
    cudaFuncSetAttribute(gemm2_mma, cudaFuncAttributeMaxDynamicSharedMemorySize, SMEM_DYN);

    __half* w1h; __half* w2h; __half* wsgh; __half* wsdh; __half* xh;
    cudaGetSymbolAddress((void**)&w1h, g_w1h);
    cudaGetSymbolAddress((void**)&w2h, g_w2h);
    cudaGetSymbolAddress((void**)&wsgh, g_wsgh);
    cudaGetSymbolAddress((void**)&wsdh, g_wsdh);
    cudaGetSymbolAddress((void**)&xh, g_xh);

    conv_kernel<<<(T_TOK * HID) / 2048, 256>>>(x, xh);
    zero_kernel<<<1, 32>>>();
    router_kernel<<<T_TOK, 128>>>(x, Wg);
    gather_kernel<<<T_TOK * TOPK, 256>>>();
    conv_kernel<<<(NEXP * 2 * IEXP * HID) / 2048, 256>>>(W1, w1h);
    gemm1_mma<<<dim3(IEXP / 64, T_TOK / 256, NEXP), 256, SMEM_DYN>>>(0);
    conv_kernel<<<(2 * ISH * HID) / 2048, 256>>>(Wsg, wsgh);
    gemm1_mma<<<dim3(ISH / 64, T_TOK / 256, 1), 256, SMEM_DYN>>>(1);
    conv_kernel<<<(NEXP * HID * IEXP) / 2048, 256>>>(W2, w2h);
    gemm2_mma<<<dim3(HID / 128, T_TOK / 256, NEXP), 256, SMEM_DYN>>>(0);
    conv_kernel<<<(HID * ISH) / 2048, 256>>>(Wsd, wsdh);
    gemm2_mma<<<dim3(HID / 128, T_TOK / 256, 1), 256, SMEM_DYN>>>(1);
    combine_kernel<<<(T_TOK * HID) / 256, 256>>>(out);
}

// round 7
// speedup vs baseline: 1.3027x; 1.3027x over previous
#include <cuda_runtime.h>
#include <cuda_fp16.h>
#include <math.h>
#include <stdint.h>

#define T_TOK 1024
#define HID   2048
#define NEXP  16
#define TOPK  4
#define IEXP  1408
#define ISH   2816

// ---------------- scratch (__device__ globals) ----------------
__device__ __align__(1024) __half g_w1h[(size_t)NEXP * 2 * IEXP * HID];
__device__ __align__(1024) __half g_w2h[(size_t)NEXP * HID * IEXP];
__device__ __align__(1024) __half g_wsgh[(size_t)2 * ISH * HID];
__device__ __align__(1024) __half g_wsdh[(size_t)HID * ISH];
__device__ __align__(1024) __half g_xh[(size_t)T_TOK * HID];
__device__ __align__(1024) __half g_xg[(size_t)NEXP * T_TOK * HID];
__device__ __align__(1024) __half g_acth[(size_t)NEXP * T_TOK * IEXP];
__device__ __align__(1024) __half g_ashh[(size_t)T_TOK * ISH];
__device__ float g_ysc[(size_t)NEXP * T_TOK * HID];
__device__ float g_sout[(size_t)T_TOK * HID];
__device__ int   g_cnt[NEXP];
__device__ int   g_te[T_TOK * TOPK];
__device__ int   g_slot[T_TOK * TOPK];
__device__ float g_tw[T_TOK * TOPK];

// ---------------- PTX helpers (plain sm_80-era PTX only) ----------------
__device__ __forceinline__ uint32_t smem_u32(const void* p) {
    uint32_t a;
    asm("{ .reg .u64 t; cvta.to.shared.u64 t, %1; cvt.u32.u64 %0, t; }" : "=r"(a) : "l"(p));
    return a;
}
#define CP16(dst, src) asm volatile("cp.async.cg.shared.global [%0], [%1], 16;" :: "r"(dst), "l"(src) : "memory")
#define CPCOMMIT()     asm volatile("cp.async.commit_group;" ::: "memory")
#define CPWAIT(n)      asm volatile("cp.async.wait_group %0;" :: "n"(n) : "memory")

__device__ __forceinline__ void ldsm4(uint32_t addr, uint32_t& r0, uint32_t& r1,
                                      uint32_t& r2, uint32_t& r3) {
    asm volatile("ldmatrix.sync.aligned.m8n8.x4.shared.b16 {%0,%1,%2,%3}, [%4];"
                 : "=r"(r0), "=r"(r1), "=r"(r2), "=r"(r3) : "r"(addr));
}
__device__ __forceinline__ void mma16816(float* c, uint32_t a0, uint32_t a1, uint32_t a2,
                                         uint32_t a3, uint32_t b0, uint32_t b1) {
    asm volatile(
        "mma.sync.aligned.m16n8k16.row.col.f32.f16.f16.f32 "
        "{%0,%1,%2,%3}, {%4,%5,%6,%7}, {%8,%9}, {%0,%1,%2,%3};"
        : "+f"(c[0]), "+f"(c[1]), "+f"(c[2]), "+f"(c[3])
        : "r"(a0), "r"(a1), "r"(a2), "r"(a3), "r"(b0), "r"(b1));
}

#define SWZ(o) ((o) ^ (((o) >> 3) & 0x70))
#define NSTAGE 3
#define STAGE_B 32768          // 16KB A (128 rows x 128B) + 16KB B (128 rows x 128B)
#define SMEM_DYN (NSTAGE * STAGE_B + 1024)

// ---------------- fp32 -> fp16 conversion ----------------
__global__ void conv_kernel(const float* __restrict__ src, __half* __restrict__ dst) {
    size_t i = ((size_t)blockIdx.x * 256 + threadIdx.x) * 8;
    float4 a = *(const float4*)(src + i);
    float4 b = *(const float4*)(src + i + 4);
    __half2 h0 = __floats2half2_rn(a.x, a.y), h1 = __floats2half2_rn(a.z, a.w);
    __half2 h2 = __floats2half2_rn(b.x, b.y), h3 = __floats2half2_rn(b.z, b.w);
    uint4 o;
    o.x = *(uint32_t*)&h0; o.y = *(uint32_t*)&h1; o.z = *(uint32_t*)&h2; o.w = *(uint32_t*)&h3;
    *(uint4*)(dst + i) = o;
}

__global__ void zero_kernel() { if (threadIdx.x < NEXP) g_cnt[threadIdx.x] = 0; }

// ---------------- router (fp32, unchanged) ----------------
__global__ void router_kernel(const float* __restrict__ x, const float* __restrict__ Wg) {
    int t = blockIdx.x;
    const float* xr = x + (size_t)t * HID;
    float acc[NEXP];
#pragma unroll
    for (int e = 0; e < NEXP; e++) acc[e] = 0.f;
    for (int h = threadIdx.x; h < HID; h += 128) {
        float xv = xr[h];
        const float* wr = Wg + (size_t)h * NEXP;
#pragma unroll
        for (int e = 0; e < NEXP; e++) acc[e] = fmaf(xv, wr[e], acc[e]);
    }
    __shared__ float red[128 * NEXP];
#pragma unroll
    for (int e = 0; e < NEXP; e++) red[threadIdx.x * NEXP + e] = acc[e];
    __syncthreads();
    __shared__ float logits[NEXP];
    if (threadIdx.x < NEXP) {
        float s = 0.f;
        for (int i = 0; i < 128; i++) s += red[i * NEXP + threadIdx.x];
        logits[threadIdx.x] = s;
    }
    __syncthreads();
    if (threadIdx.x == 0) {
        float lv[NEXP];
#pragma unroll
        for (int e = 0; e < NEXP; e++) lv[e] = logits[e];
        int ids[TOPK]; float vals[TOPK];
        bool used[NEXP];
#pragma unroll
        for (int e = 0; e < NEXP; e++) used[e] = false;
        for (int k = 0; k < TOPK; k++) {
            int bi = 0; float bv = -3.4e38f;
            for (int e = 0; e < NEXP; e++)
                if (!used[e] && lv[e] > bv) { bv = lv[e]; bi = e; }
            used[bi] = true; ids[k] = bi; vals[k] = bv;
        }
        float m = vals[0], ssum = 0.f, wv[TOPK];
        for (int k = 0; k < TOPK; k++) { wv[k] = expf(vals[k] - m); ssum += wv[k]; }
        float inv = 1.f / ssum;
        for (int k = 0; k < TOPK; k++) {
            int e = ids[k];
            int slot = atomicAdd(&g_cnt[e], 1);
            g_te[t * TOPK + k]   = e;
            g_slot[t * TOPK + k] = slot;
            g_tw[t * TOPK + k]   = wv[k] * inv;
        }
    }
}

// ---------------- gather x rows (fp16) into per-expert contiguous buffers ----------------
__global__ void gather_kernel() {
    int b = blockIdx.x;
    int t = b >> 2, k = b & 3;
    int e = g_te[t * TOPK + k], slot = g_slot[t * TOPK + k];
    const uint4* src = (const uint4*)(g_xh + (size_t)t * HID);
    uint4* dst = (uint4*)(g_xg + ((size_t)e * T_TOK + slot) * HID);
    dst[threadIdx.x] = src[threadIdx.x];
}

// ---------------- gemm1: block 128 rows x 64 out-cols (B tile = 64 gate + 64 up rows) ----
// 128 threads, 4 warps as 2m x 2n; warp tile = 64 rows x (32 gate + 32 up cols).
__global__ void __launch_bounds__(128) gemm1_mma(int shared_mode) {
    int e = blockIdx.z;
    const __half* A; const __half* B; __half* act;
    int nrows, Ihalf;
    const int K = HID;
    if (shared_mode) { A = g_xh; B = g_wsgh; act = g_ashh; nrows = T_TOK; Ihalf = ISH; }
    else {
        A = g_xg + (size_t)e * T_TOK * HID;
        B = g_w1h + (size_t)e * 2 * IEXP * HID;
        act = g_acth + (size_t)e * T_TOK * IEXP;
        nrows = g_cnt[e]; Ihalf = IEXP;
    }
    int m0 = blockIdx.y * 128;
    if (m0 >= nrows) return;
    int j0 = blockIdx.x * 64;

    extern __shared__ char smraw[];
    uint32_t sb = (smem_u32(smraw) + 1023) & ~1023u;
    int tid = threadIdx.x, lane = tid & 31, wid = tid >> 5;
    int wm = wid & 1, wn = wid >> 1;

    // loaders: A = 1024 16B-chunks (8/thread, row stride 16), B same.
    int r0 = tid >> 3, c16 = tid & 7;
    const __half* abase = A + (size_t)(m0 + r0) * K + c16 * 8;          // i: +16*K
    const __half* bbase0 = B + (size_t)(j0 + r0) * K + c16 * 8;        // i=0..3 (gate rows 0..63)
    const __half* bbase1 = B + (size_t)(Ihalf + j0 + r0) * K + c16 * 8; // i=4..7 (up rows 64..127)
    uint32_t swzb = SWZ((uint32_t)(r0 * 128 + c16 * 16));               // i: +2048 (swizzle-invariant)

    const int KT = K / 64;
    for (int s = 0; s < NSTAGE - 1; s++) {
        uint32_t sA = sb + s * STAGE_B, sB = sA + 16384;
        int ko = s * 64;
#pragma unroll
        for (int i = 0; i < 8; i++) CP16(sA + swzb + i * 2048, abase + (size_t)i * 16 * K + ko);
#pragma unroll
        for (int i = 0; i < 4; i++) CP16(sB + swzb + i * 2048, bbase0 + (size_t)i * 16 * K + ko);
#pragma unroll
        for (int i = 0; i < 4; i++) CP16(sB + swzb + (i + 4) * 2048, bbase1 + (size_t)i * 16 * K + ko);
        CPCOMMIT();
    }

    // ct[mi][ni][4]: mi 0..3 (16-row tiles), ni 0..3 gate cols, 4..7 up cols
    float ct[4][8][4];
#pragma unroll
    for (int mi = 0; mi < 4; mi++)
#pragma unroll
        for (int j = 0; j < 8; j++)
#pragma unroll
            for (int q = 0; q < 4; q++) ct[mi][j][q] = 0.f;

    uint32_t l15 = (uint32_t)(lane & 15);
    uint32_t kcb = ((lane >> 4) << 4);

    for (int kt = 0; kt < KT; kt++) {
        CPWAIT(1);
        __syncthreads();
        uint32_t sA = sb + (kt % NSTAGE) * STAGE_B, sB = sA + 16384;
#pragma unroll
        for (int ks = 0; ks < 4; ks++) {
            uint32_t a[4][4];
#pragma unroll
            for (int mi = 0; mi < 4; mi++)
                ldsm4(sA + SWZ((uint32_t)((wm * 64 + mi * 16 + l15) * 128) + ks * 32 + kcb),
                      a[mi][0], a[mi][1], a[mi][2], a[mi][3]);
#pragma unroll
            for (int bb = 0; bb < 2; bb++) {   // gate rows
                uint32_t b0, b1, b2, b3;
                ldsm4(sB + SWZ((uint32_t)((wn * 32 + bb * 16 + l15) * 128) + ks * 32 + kcb), b0, b1, b2, b3);
#pragma unroll
                for (int mi = 0; mi < 4; mi++) {
                    mma16816(ct[mi][2 * bb],     a[mi][0], a[mi][1], a[mi][2], a[mi][3], b0, b2);
                    mma16816(ct[mi][2 * bb + 1], a[mi][0], a[mi][1], a[mi][2], a[mi][3], b1, b3);
                }
            }
#pragma unroll
            for (int bb = 0; bb < 2; bb++) {   // up rows (B smem rows 64..127)
                uint32_t b0, b1, b2, b3;
                ldsm4(sB + SWZ((uint32_t)((64 + wn * 32 + bb * 16 + l15) * 128) + ks * 32 + kcb), b0, b1, b2, b3);
#pragma unroll
                for (int mi = 0; mi < 4; mi++) {
                    mma16816(ct[mi][4 + 2 * bb],     a[mi][0], a[mi][1], a[mi][2], a[mi][3], b0, b2);
                    mma16816(ct[mi][4 + 2 * bb + 1], a[mi][0], a[mi][1], a[mi][2], a[mi][3], b1, b3);
                }
            }
        }
        __syncthreads();
        int nc = kt + NSTAGE - 1;
        if (nc < KT) {
            uint32_t dA = sb + (nc % NSTAGE) * STAGE_B, dB = dA + 16384;
            int ko = nc * 64;
#pragma unroll
            for (int i = 0; i < 8; i++) CP16(dA + swzb + i * 2048, abase + (size_t)i * 16 * K + ko);
#pragma unroll
            for (int i = 0; i < 4; i++) CP16(dB + swzb + i * 2048, bbase0 + (size_t)i * 16 * K + ko);
#pragma unroll
            for (int i = 0; i < 4; i++) CP16(dB + swzb + (i + 4) * 2048, bbase1 + (size_t)i * 16 * K + ko);
        }
        CPCOMMIT();
    }

#pragma unroll
    for (int mi = 0; mi < 4; mi++) {
        int row = m0 + wm * 64 + mi * 16 + (lane >> 2);
#pragma unroll
        for (int ni = 0; ni < 4; ni++) {
            int col = j0 + wn * 32 + ni * 8 + (lane & 3) * 2;
            if (row < nrows) {
                float g0 = ct[mi][ni][0], g1 = ct[mi][ni][1];
                float u0 = ct[mi][ni + 4][0], u1 = ct[mi][ni + 4][1];
                __half2 h = __floats2half2_rn(g0 / (1.f + expf(-g0)) * u0,
                                              g1 / (1.f + expf(-g1)) * u1);
                *(__half2*)(act + (size_t)row * Ihalf + col) = h;
            }
            if (row + 8 < nrows) {
                float g0 = ct[mi][ni][2], g1 = ct[mi][ni][3];
                float u0 = ct[mi][ni + 4][2], u1 = ct[mi][ni + 4][3];
                __half2 h = __floats2half2_rn(g0 / (1.f + expf(-g0)) * u0,
                                              g1 / (1.f + expf(-g1)) * u1);
                *(__half2*)(act + (size_t)(row + 8) * Ihalf + col) = h;
            }
        }
    }
}

// ---------------- gemm2: block 128 x 128, 4 warps 2m x 2n, warp 64x64 -> fp32 ----------------
__global__ void __launch_bounds__(128) gemm2_mma(int shared_mode) {
    int e = blockIdx.z;
    const __half* A; const __half* B; float* C;
    int nrows, K;
    if (shared_mode) { A = g_ashh; B = g_wsdh; C = g_sout; nrows = T_TOK; K = ISH; }
    else {
        A = g_acth + (size_t)e * T_TOK * IEXP;
        B = g_w2h + (size_t)e * HID * IEXP;
        C = g_ysc + (size_t)e * T_TOK * HID;
        nrows = g_cnt[e]; K = IEXP;
    }
    int m0 = blockIdx.y * 128;
    if (m0 >= nrows) return;
    int n0 = blockIdx.x * 128;

    extern __shared__ char smraw[];
    uint32_t sb = (smem_u32(smraw) + 1023) & ~1023u;
    int tid = threadIdx.x, lane = tid & 31, wid = tid >> 5;
    int wm = wid & 1, wn = wid >> 1;

    int r0 = tid >> 3, c16 = tid & 7;
    const __half* abase = A + (size_t)(m0 + r0) * K + c16 * 8;
    const __half* bbase = B + (size_t)(n0 + r0) * K + c16 * 8;
    uint32_t swzb = SWZ((uint32_t)(r0 * 128 + c16 * 16));

    const int KT = K / 64;
    for (int s = 0; s < NSTAGE - 1; s++) {
        uint32_t sA = sb + s * STAGE_B, sB = sA + 16384;
        int ko = s * 64;
#pragma unroll
        for (int i = 0; i < 8; i++) {
            CP16(sA + swzb + i * 2048, abase + (size_t)i * 16 * K + ko);
            CP16(sB + swzb + i * 2048, bbase + (size_t)i * 16 * K + ko);
        }
        CPCOMMIT();
    }

    float ct[4][8][4];
#pragma unroll
    for (int mi = 0; mi < 4; mi++)
#pragma unroll
        for (int j = 0; j < 8; j++)
#pragma unroll
            for (int q = 0; q < 4; q++) ct[mi][j][q] = 0.f;

    uint32_t l15 = (uint32_t)(lane & 15);
    uint32_t kcb = ((lane >> 4) << 4);

    for (int kt = 0; kt < KT; kt++) {
        CPWAIT(1);
        __syncthreads();
        uint32_t sA = sb + (kt % NSTAGE) * STAGE_B, sB = sA + 16384;
#pragma unroll
        for (int ks = 0; ks < 4; ks++) {
            uint32_t a[4][4];
#pragma unroll
            for (int mi = 0; mi < 4; mi++)
                ldsm4(sA + SWZ((uint32_t)((wm * 64 + mi * 16 + l15) * 128) + ks * 32 + kcb),
                      a[mi][0], a[mi][1], a[mi][2], a[mi][3]);
#pragma unroll
            for (int bb = 0; bb < 4; bb++) {
                uint32_t b0, b1, b2, b3;
                ldsm4(sB + SWZ((uint32_t)((wn * 64 + bb * 16 + l15) * 128) + ks * 32 + kcb), b0, b1, b2, b3);
#pragma unroll
                for (int mi = 0; mi < 4; mi++) {
                    mma16816(ct[mi][2 * bb],     a[mi][0], a[mi][1], a[mi][2], a[mi][3], b0, b2);
                    mma16816(ct[mi][2 * bb + 1], a[mi][0], a[mi][1], a[mi][2], a[mi][3], b1, b3);
                }
            }
        }
        __syncthreads();
        int nc = kt + NSTAGE - 1;
        if (nc < KT) {
            uint32_t dA = sb + (nc % NSTAGE) * STAGE_B, dB = dA + 16384;
            int ko = nc * 64;
#pragma unroll
            for (int i = 0; i < 8; i++) {
                CP16(dA + swzb + i * 2048, abase + (size_t)i * 16 * K + ko);
                CP16(dB + swzb + i * 2048, bbase + (size_t)i * 16 * K + ko);
            }
        }
        CPCOMMIT();
    }

#pragma unroll
    for (int mi = 0; mi < 4; mi++) {
        int row = m0 + wm * 64 + mi * 16 + (lane >> 2);
#pragma unroll
        for (int ni = 0; ni < 8; ni++) {
            int col = n0 + wn * 64 + ni * 8 + (lane & 3) * 2;
            if (row < nrows)
                *(float2*)(C + (size_t)row * HID + col) = make_float2(ct[mi][ni][0], ct[mi][ni][1]);
            if (row + 8 < nrows)
                *(float2*)(C + (size_t)(row + 8) * HID + col) = make_float2(ct[mi][ni][2], ct[mi][ni][3]);
        }
    }
}

// ---------------- combine ----------------
__global__ void combine_kernel(float* __restrict__ out) {
    size_t idx = (size_t)blockIdx.x * 256 + threadIdx.x;
    int t = (int)(idx >> 11);
    int h = (int)(idx & 2047);
    float v = g_sout[idx];
#pragma unroll
    for (int k = 0; k < TOPK; k++) {
        int e = g_te[t * TOPK + k];
        int s = g_slot[t * TOPK + k];
        float w = g_tw[t * TOPK + k];
        v = fmaf(w, g_ysc[((size_t)e * T_TOK + s) * HID + h], v);
    }
    out[idx] = v;
}

extern "C" void kernel_launch(void* const* d_in, const int* in_sizes, int n_in,
                              void* d_out, int out_size) {
    const float* x   = (const float*)d_in[0];
    const float* Wg  = (const float*)d_in[1];
    const float* W1  = (const float*)d_in[2];
    const float* W2  = (const float*)d_in[3];
    const float* Wsg = (const float*)d_in[4];
    const float* Wsd = (const float*)d_in[5];
    float* out = (float*)d_out;

    cudaFuncSetAttribute(gemm1_mma, cudaFuncAttributeMaxDynamicSharedMemorySize, SMEM_DYN);
    cudaFuncSetAttribute(gemm2_mma, cudaFuncAttributeMaxDynamicSharedMemorySize, SMEM_DYN);

    __half* w1h; __half* w2h; __half* wsgh; __half* wsdh; __half* xh;
    cudaGetSymbolAddress((void**)&w1h, g_w1h);
    cudaGetSymbolAddress((void**)&w2h, g_w2h);
    cudaGetSymbolAddress((void**)&wsgh, g_wsgh);
    cudaGetSymbolAddress((void**)&wsdh, g_wsdh);
    cudaGetSymbolAddress((void**)&xh, g_xh);

    conv_kernel<<<(T_TOK * HID) / 2048, 256>>>(x, xh);
    zero_kernel<<<1, 32>>>();
    router_kernel<<<T_TOK, 128>>>(x, Wg);
    gather_kernel<<<T_TOK * TOPK, 256>>>();
    conv_kernel<<<(NEXP * 2 * IEXP * HID) / 2048, 256>>>(W1, w1h);
    gemm1_mma<<<dim3(IEXP / 64, T_TOK / 128, NEXP), 128, SMEM_DYN>>>(0);
    conv_kernel<<<(2 * ISH * HID) / 2048, 256>>>(Wsg, wsgh);
    gemm1_mma<<<dim3(ISH / 64, T_TOK / 128, 1), 128, SMEM_DYN>>>(1);
    conv_kernel<<<(NEXP * HID * IEXP) / 2048, 256>>>(W2, w2h);
    gemm2_mma<<<dim3(HID / 128, T_TOK / 128, NEXP), 128, SMEM_DYN>>>(0);
    conv_kernel<<<(HID * ISH) / 2048, 256>>>(Wsd, wsdh);
    gemm2_mma<<<dim3(HID / 128, T_TOK / 128, 1), 128, SMEM_DYN>>>(1);
    combine_kernel<<<(T_TOK * HID) / 256, 256>>>(out);
}